// round 3
// baseline (speedup 1.0000x reference)
#include <cuda_runtime.h>
#include <cuda_bf16.h>
#include <math.h>

// Problem constants (fixed shapes)
#define NN   4096      // N = V*B
#define BB   2048      // batch
#define VV   2         // views
#define DD   256       // feature dim
#define CC   1000      // classes
#define TEMP 0.07f

// Scratch (no cudaMalloc allowed)
__device__ float g_cf[NN * DD];   // normalized, view-major stacked features [N, D]
__device__ float g_mod[BB];       // focal modulation per sample
__device__ float g_S[NN];         // sum exp(l - M) over j != i
__device__ float g_P[NN];         // sum over positives of (l - M)
__device__ float g_cnt[NN];       // positive counts

// ---------------------------------------------------------------------------
// K0: normalize rows + view-major restack + zero accumulators
// features [B, V, D] -> g_cf[v*B + b][:]
// one warp per output row
// ---------------------------------------------------------------------------
__global__ void norm_kernel(const float* __restrict__ feats) {
    int gw   = (blockIdx.x * blockDim.x + threadIdx.x) >> 5;
    int lane = threadIdx.x & 31;
    if (gw >= NN) return;
    int b = gw & (BB - 1);
    int v = gw >> 11;

    const float4* src = reinterpret_cast<const float4*>(feats + (size_t)(b * VV + v) * DD);
    float4 x0 = src[lane];
    float4 x1 = src[lane + 32];

    float ss = x0.x * x0.x + x0.y * x0.y + x0.z * x0.z + x0.w * x0.w
             + x1.x * x1.x + x1.y * x1.y + x1.z * x1.z + x1.w * x1.w;
#pragma unroll
    for (int o = 16; o > 0; o >>= 1) ss += __shfl_xor_sync(0xffffffffu, ss, o);
    float inv = rsqrtf(ss);

    float4 y0 = make_float4(x0.x * inv, x0.y * inv, x0.z * inv, x0.w * inv);
    float4 y1 = make_float4(x1.x * inv, x1.y * inv, x1.z * inv, x1.w * inv);
    float4* dst = reinterpret_cast<float4*>(g_cf + (size_t)gw * DD);
    dst[lane]      = y0;
    dst[lane + 32] = y1;

    if (lane == 0) {   // zero accumulators every replay (graph-safe)
        g_S[gw] = 0.f; g_P[gw] = 0.f; g_cnt[gw] = 0.f;
    }
}

// ---------------------------------------------------------------------------
// K1: focal modulation per sample: mod = (1 - exp(log_softmax(preds)[label]))^2
// one block (128 threads) per sample b
// ---------------------------------------------------------------------------
__device__ __forceinline__ float warp_max(float v) {
#pragma unroll
    for (int o = 16; o > 0; o >>= 1) v = fmaxf(v, __shfl_xor_sync(0xffffffffu, v, o));
    return v;
}
__device__ __forceinline__ float warp_sum(float v) {
#pragma unroll
    for (int o = 16; o > 0; o >>= 1) v += __shfl_xor_sync(0xffffffffu, v, o);
    return v;
}

__global__ void mod_kernel(const float* __restrict__ preds, const int* __restrict__ labels) {
    __shared__ float sh4[4];
    int b = blockIdx.x, t = threadIdx.x, lane = t & 31, w = t >> 5;
    const float* row = preds + (size_t)b * CC;

    float mx = -1e30f;
    for (int c = t; c < CC; c += 128) mx = fmaxf(mx, row[c]);
    mx = warp_max(mx);
    if (lane == 0) sh4[w] = mx;
    __syncthreads();
    mx = fmaxf(fmaxf(sh4[0], sh4[1]), fmaxf(sh4[2], sh4[3]));
    __syncthreads();

    float s = 0.f;
    for (int c = t; c < CC; c += 128) s += __expf(row[c] - mx);
    s = warp_sum(s);
    if (lane == 0) sh4[w] = s;
    __syncthreads();

    if (t == 0) {
        float ssum = sh4[0] + sh4[1] + sh4[2] + sh4[3];
        float nll  = row[labels[b]] - mx - logf(ssum);  // log p_t
        float pt   = __expf(nll);
        float om   = 1.f - pt;
        g_mod[b]   = om * om;    // GAMMA = 2
    }
}

// ---------------------------------------------------------------------------
// K2: fused similarity GEMM + row reductions.
// Block = 64 rows x 1024-column strip. Grid (64, 4). 256 threads.
// Shared tiles stored k-major: As[256][68], Bs[64][68] (pad=4 floats).
// Microtile 4x4 per thread: per-k = 2x LDS.128 + 16 FFMA.
// Shift M = 1/T applied analytically (cancels exactly vs reference's row max).
// ---------------------------------------------------------------------------
#define WPAD 68
#define K2_SMEM ((256 * WPAD + 64 * WPAD) * 4)

__global__ void __launch_bounds__(256) main_kernel(const int* __restrict__ labels) {
    extern __shared__ float sh[];
    float* As = sh;                 // [256][WPAD] k-major, full D for 64 rows
    float* Bs = sh + 256 * WPAD;    // [64][WPAD]  k-major, BK=64 chunk for 64 cols
    __shared__ float sS[64], sP[64], sC[64];
    __shared__ int   cl[64];

    const int tid = threadIdx.x;
    const int tr = tid >> 4;        // 0..15 -> rows tr*4..tr*4+3
    const int tc = tid & 15;        // 0..15 -> cols tc*4..tc*4+3
    const int i0 = blockIdx.x * 64;
    const int jbase = blockIdx.y * 1024;

    if (tid < 64) { sS[tid] = 0.f; sP[tid] = 0.f; sC[tid] = 0.f; }

    // Fill As (once): rows i0..i0+63, all 256 k, transposed to k-major.
    {
        int r   = tid >> 2;
        int kq0 = tid & 3;
        const float4* src = reinterpret_cast<const float4*>(g_cf + (size_t)(i0 + r) * DD);
#pragma unroll
        for (int it = 0; it < 16; ++it) {
            int kq = kq0 + (it << 2);
            float4 vv = src[kq];
            int kb = kq << 2;
            As[(kb + 0) * WPAD + r] = vv.x;
            As[(kb + 1) * WPAD + r] = vv.y;
            As[(kb + 2) * WPAD + r] = vv.z;
            As[(kb + 3) * WPAD + r] = vv.w;
        }
    }

    int rl[4];
#pragma unroll
    for (int m = 0; m < 4; ++m) rl[m] = labels[(i0 + tr * 4 + m) & (BB - 1)];

    float s_acc[4] = {0.f, 0.f, 0.f, 0.f};
    float p_acc[4] = {0.f, 0.f, 0.f, 0.f};
    float c_acc[4] = {0.f, 0.f, 0.f, 0.f};

    const float invT = 1.0f / TEMP;

    for (int jt = 0; jt < 16; ++jt) {
        const int j0 = jbase + jt * 64;
        float acc[4][4];
#pragma unroll
        for (int m = 0; m < 4; ++m)
#pragma unroll
            for (int n = 0; n < 4; ++n) acc[m][n] = 0.f;

        for (int kc = 0; kc < 4; ++kc) {
            __syncthreads();
            // fill Bs chunk: cols j0..j0+63, k in [kc*64, kc*64+64)
            {
                int c   = tid >> 2;
                int kq0 = tid & 3;
                const float4* src = reinterpret_cast<const float4*>(
                    g_cf + (size_t)(j0 + c) * DD + kc * 64);
#pragma unroll
                for (int it = 0; it < 4; ++it) {
                    int kq = kq0 + (it << 2);
                    float4 vv = src[kq];
                    int kb = kq << 2;
                    Bs[(kb + 0) * WPAD + c] = vv.x;
                    Bs[(kb + 1) * WPAD + c] = vv.y;
                    Bs[(kb + 2) * WPAD + c] = vv.z;
                    Bs[(kb + 3) * WPAD + c] = vv.w;
                }
            }
            if (kc == 0 && tid < 64) cl[tid] = labels[(j0 + tid) & (BB - 1)];
            __syncthreads();

            const float* Ab = As + kc * 64 * WPAD;
#pragma unroll 8
            for (int k = 0; k < 64; ++k) {
                float4 a = *reinterpret_cast<const float4*>(Ab + k * WPAD + tr * 4);
                float4 b = *reinterpret_cast<const float4*>(Bs + k * WPAD + tc * 4);
                acc[0][0] += a.x * b.x; acc[0][1] += a.x * b.y;
                acc[0][2] += a.x * b.z; acc[0][3] += a.x * b.w;
                acc[1][0] += a.y * b.x; acc[1][1] += a.y * b.y;
                acc[1][2] += a.y * b.z; acc[1][3] += a.y * b.w;
                acc[2][0] += a.z * b.x; acc[2][1] += a.z * b.y;
                acc[2][2] += a.z * b.z; acc[2][3] += a.z * b.w;
                acc[3][0] += a.w * b.x; acc[3][1] += a.w * b.y;
                acc[3][2] += a.w * b.z; acc[3][3] += a.w * b.w;
            }
        }

        // Epilogue for this 64x64 tile: exp-sum / masked-logit-sum / counts
#pragma unroll
        for (int m = 0; m < 4; ++m) {
            const int i = i0 + tr * 4 + m;
#pragma unroll
            for (int n = 0; n < 4; ++n) {
                const int j = j0 + tc * 4 + n;
                float l = acc[m][n] * invT - invT;   // logits - M, M = 1/T
                if (i != j) {
                    s_acc[m] += __expf(l);
                    if (rl[m] == cl[tc * 4 + n]) { p_acc[m] += l; c_acc[m] += 1.f; }
                }
            }
        }
    }

    // Cross-thread (tc) reduction per row via shared atomics, then one global
    // atomic per row per block (4 column-strip blocks contribute per row).
#pragma unroll
    for (int m = 0; m < 4; ++m) {
        atomicAdd(&sS[tr * 4 + m], s_acc[m]);
        atomicAdd(&sP[tr * 4 + m], p_acc[m]);
        atomicAdd(&sC[tr * 4 + m], c_acc[m]);
    }
    __syncthreads();
    if (tid < 64) {
        atomicAdd(&g_S[i0 + tid],   sS[tid]);
        atomicAdd(&g_P[i0 + tid],   sP[tid]);
        atomicAdd(&g_cnt[i0 + tid], sC[tid]);
    }
}

// ---------------------------------------------------------------------------
// K3: per-row loss + mean
// loss_i = -mod[i%B] * (P_i/cnt_i - log S_i);  out = mean_i loss_i
// ---------------------------------------------------------------------------
__global__ void finalize_kernel(float* __restrict__ out) {
    __shared__ float red[256];
    int t = threadIdx.x;
    float acc = 0.f;
    for (int i = t; i < NN; i += 256) {
        float lp = g_P[i] / g_cnt[i] - logf(g_S[i]);
        acc += g_mod[i & (BB - 1)] * lp;
    }
    red[t] = acc;
    __syncthreads();
#pragma unroll
    for (int s = 128; s > 0; s >>= 1) {
        if (t < s) red[t] += red[t + s];
        __syncthreads();
    }
    if (t == 0) out[0] = -red[0] / (float)NN;
}

// ---------------------------------------------------------------------------
extern "C" void kernel_launch(void* const* d_in, const int* in_sizes, int n_in,
                              void* d_out, int out_size) {
    const float* feats  = (const float*)d_in[0];   // [B, V, D]
    const float* preds  = (const float*)d_in[1];   // [B, C]
    const int*   labels = (const int*)d_in[2];     // [B]
    float* out = (float*)d_out;

    cudaFuncSetAttribute(main_kernel, cudaFuncAttributeMaxDynamicSharedMemorySize, K2_SMEM);

    norm_kernel<<<NN / 8, 256>>>(feats);           // 8 rows (warps) per block
    mod_kernel<<<BB, 128>>>(preds, labels);
    main_kernel<<<dim3(NN / 64, 4), 256, K2_SMEM>>>(labels);
    finalize_kernel<<<1, 256>>>(out);
}

// round 5
// speedup vs baseline: 3.1447x; 3.1447x over previous
#include <cuda_runtime.h>
#include <cuda_bf16.h>
#include <math.h>
#include <stdint.h>

// Problem constants (fixed shapes)
#define NN   4096      // N = V*B
#define BB   2048      // batch
#define VV   2         // views
#define DD   256       // feature dim
#define CC   1000      // classes
#define TEMP 0.07f

// Scratch (no cudaMalloc allowed)
__device__ __nv_bfloat16 g_hi[NN * DD];   // bf16 high part of normalized features
__device__ __nv_bfloat16 g_lo[NN * DD];   // bf16 residual (lo) part
__device__ float g_mod[BB];               // focal modulation per sample
__device__ float g_S[NN];                 // sum exp(l - M) over j != i
__device__ float g_P[NN];                 // sum over positives of (l - M)
__device__ float g_cnt[NN];               // positive counts
__device__ float g_part[32];              // finalize partials

// ============================================================================
// Generic PTX helpers (valid on compute_103 base target)
// ============================================================================
__device__ __forceinline__ uint32_t smem_to_u32(const void* p) {
    uint32_t a;
    asm("{ .reg .u64 t; cvta.to.shared.u64 t, %1; cvt.u32.u64 %0, t; }"
        : "=r"(a) : "l"(p));
    return a;
}
#define SMEM_SWIZZLE_128B(byte_offset) \
    ((byte_offset) ^ (((byte_offset) >> 3) & 0x70))

// mma.sync bf16 (sm_80+, arch-agnostic): D(16x8 f32) += A(16x16) * B(16x8)
#define MMA_BF16(d, a, b0, b1) \
    asm volatile("mma.sync.aligned.m16n8k16.row.col.f32.bf16.bf16.f32 " \
        "{%0,%1,%2,%3}, {%4,%5,%6,%7}, {%8,%9}, {%0,%1,%2,%3};" \
        : "+f"((d)[0]), "+f"((d)[1]), "+f"((d)[2]), "+f"((d)[3]) \
        : "r"((a)[0]), "r"((a)[1]), "r"((a)[2]), "r"((a)[3]), \
          "r"(b0), "r"(b1))

#define LDSM_X4(r0, r1, r2, r3, addr) \
    asm volatile("ldmatrix.sync.aligned.m8n8.x4.shared.b16 {%0,%1,%2,%3}, [%4];" \
        : "=r"(r0), "=r"(r1), "=r"(r2), "=r"(r3) : "r"(addr))

#define CP_ASYNC_16(dst, src) \
    asm volatile("cp.async.cg.shared.global [%0], [%1], 16;" \
        :: "r"(dst), "l"(src) : "memory")
#define CP_ASYNC_COMMIT() asm volatile("cp.async.commit_group;" ::: "memory")
#define CP_ASYNC_WAIT(n)  asm volatile("cp.async.wait_group %0;" :: "n"(n) : "memory")

// ============================================================================
// sm_103a-only helpers (tcgen05) — compiled only when feature macro present
// ============================================================================
#if defined(__CUDA_ARCH_FEAT_SM103_ALL) || defined(__CUDA_ARCH_FEAT_SM100_ALL)
__device__ __forceinline__ uint32_t elect_one_pred() {
    uint32_t pred;
    asm volatile("{\n\t.reg .pred p;\n\telect.sync _|p, 0xFFFFFFFF;\n\t"
                 "selp.b32 %0, 1, 0, p;\n\t}" : "=r"(pred));
    return pred;
}
#define MBARRIER_INIT(mbar, count) \
    asm volatile("mbarrier.init.shared.b64 [%0], %1;" \
        :: "r"((uint32_t)(mbar)), "r"((uint32_t)(count)) : "memory")
#define MBARRIER_WAIT_PARITY(mbar_smem_addr, phase_parity) do { \
    uint32_t _mbar = (uint32_t)(mbar_smem_addr); \
    uint32_t _parity = (uint32_t)(phase_parity); \
    uint32_t _done; \
    asm volatile("{\n\t.reg .pred p;\n\t" \
        "mbarrier.try_wait.parity.acquire.cta.shared::cta.b64 p, [%1], %2;\n\t" \
        "selp.b32 %0, 1, 0, p;\n\t}" \
        : "=r"(_done) : "r"(_mbar), "r"(_parity) : "memory"); \
    if (!_done) { \
        asm volatile("{\n\t.reg .pred P1;\n\t" \
            "WAIT_LOOP_%=:\n\t" \
            "mbarrier.try_wait.parity.acquire.cta.shared::cta.b64 P1, [%0], %1, 0x989680;\n\t" \
            "@P1 bra.uni WAIT_DONE_%=;\n\t" \
            "bra.uni WAIT_LOOP_%=;\n\t" \
            "WAIT_DONE_%=:\n\t}" \
            :: "r"(_mbar), "r"(_parity) : "memory"); \
    } \
} while(0)
__device__ __forceinline__ void mbarrier_inval(uint32_t mbar) {
    asm volatile("mbarrier.inval.shared.b64 [%0];" :: "r"(mbar) : "memory");
}
#define TCGEN05_ALLOC(smem_result_addr, nCols) \
    asm volatile("tcgen05.alloc.cta_group::1.sync.aligned.shared::cta.b32 [%0], %1;" \
        :: "r"((uint32_t)(smem_result_addr)), "r"((uint32_t)(nCols)) : "memory")
#define TCGEN05_DEALLOC(tmem_addr, nCols) \
    asm volatile("tcgen05.dealloc.cta_group::1.sync.aligned.b32 %0, %1;" \
        :: "r"(tmem_addr), "r"((uint32_t)(nCols)))
#define TCGEN05_COMMIT(mbar_smem_addr) \
    asm volatile("tcgen05.commit.cta_group::1.mbarrier::arrive::one.shared::cluster.b64 [%0];" \
        :: "r"((uint32_t)(mbar_smem_addr)) : "memory")
#define TCGEN05_FENCE_AFTER() \
    asm volatile("tcgen05.fence::after_thread_sync;" ::: "memory")
#define TCGEN05_FENCE_BEFORE() \
    asm volatile("tcgen05.fence::before_thread_sync;" ::: "memory")
#define TCGEN05_WAIT_LD() \
    asm volatile("tcgen05.wait::ld.sync.aligned;" ::: "memory")
#define FENCE_PROXY_ASYNC_SHARED_CTA() \
    asm volatile("fence.proxy.async.shared::cta;" ::: "memory")
#define TCGEN05_LD_32X32B_X32(r, tmem_addr) \
    asm volatile("tcgen05.ld.sync.aligned.32x32b.x32.b32 " \
        "{%0, %1, %2, %3, %4, %5, %6, %7, " \
        " %8, %9, %10, %11, %12, %13, %14, %15, " \
        " %16, %17, %18, %19, %20, %21, %22, %23, " \
        " %24, %25, %26, %27, %28, %29, %30, %31}, [%32];" \
        : "=r"((r)[0]),  "=r"((r)[1]),  "=r"((r)[2]),  "=r"((r)[3]), \
          "=r"((r)[4]),  "=r"((r)[5]),  "=r"((r)[6]),  "=r"((r)[7]), \
          "=r"((r)[8]),  "=r"((r)[9]),  "=r"((r)[10]), "=r"((r)[11]), \
          "=r"((r)[12]), "=r"((r)[13]), "=r"((r)[14]), "=r"((r)[15]), \
          "=r"((r)[16]), "=r"((r)[17]), "=r"((r)[18]), "=r"((r)[19]), \
          "=r"((r)[20]), "=r"((r)[21]), "=r"((r)[22]), "=r"((r)[23]), \
          "=r"((r)[24]), "=r"((r)[25]), "=r"((r)[26]), "=r"((r)[27]), \
          "=r"((r)[28]), "=r"((r)[29]), "=r"((r)[30]), "=r"((r)[31]) \
        : "r"(tmem_addr))

static constexpr uint64_t SMEM_DESC_BASE_SW128 =
    (uint64_t(2)  << 61) | (uint64_t(1) << 46) | (uint64_t(64) << 32) | (uint64_t(1) << 16);
#define MAKE_SMEM_DESC(base_addr) \
    (SMEM_DESC_BASE_SW128 | ((uint64_t)((base_addr) >> 4) & 0x3FFF))

__device__ __forceinline__ void mma_ss_f16(
    uint32_t d_tmem, uint64_t a_desc, uint64_t b_desc, uint32_t idesc, bool en)
{
    uint32_t e = en ? 1u : 0u;
    asm volatile(
        "{\n\t.reg .pred p;\n\tsetp.ne.u32 p, %5, 0;\n\t"
        "tcgen05.mma.cta_group::1.kind::f16 [%0], %1, %2, %3, {%4, %4, %4, %4}, p;\n\t}"
        :: "r"(d_tmem), "l"(a_desc), "l"(b_desc), "r"(idesc), "r"(0u), "r"(e)
        : "memory");
}
// idesc: dtype=F32 (1<<4), atype=BF16 (1<<7), btype=BF16 (1<<10), N=256, M=128
#define IDESC_MAIN ((1u<<4) | (1u<<7) | (1u<<10) | ((256u/8)<<17) | ((128u/16)<<24))
#endif // sm_103a feature

// ---------------------------------------------------------------------------
// K0: normalize rows + view-major restack + split fp32 -> (hi, lo) bf16
// ---------------------------------------------------------------------------
__device__ __forceinline__ void split_bf16(float x, __nv_bfloat16& h, __nv_bfloat16& l) {
    h = __float2bfloat16(x);
    l = __float2bfloat16(x - __bfloat162float(h));
}

__global__ void norm_kernel(const float* __restrict__ feats) {
    int gw   = (blockIdx.x * blockDim.x + threadIdx.x) >> 5;
    int lane = threadIdx.x & 31;
    if (gw >= NN) return;
    int b = gw & (BB - 1);
    int v = gw >> 11;

    const float4* src = reinterpret_cast<const float4*>(feats + (size_t)(b * VV + v) * DD);
    float4 x0 = src[lane];
    float4 x1 = src[lane + 32];

    float ss = x0.x * x0.x + x0.y * x0.y + x0.z * x0.z + x0.w * x0.w
             + x1.x * x1.x + x1.y * x1.y + x1.z * x1.z + x1.w * x1.w;
#pragma unroll
    for (int o = 16; o > 0; o >>= 1) ss += __shfl_xor_sync(0xffffffffu, ss, o);
    float inv = rsqrtf(ss);

    __nv_bfloat16* hp = g_hi + (size_t)gw * DD;
    __nv_bfloat16* lp = g_lo + (size_t)gw * DD;
    float vals[8] = { x0.x*inv, x0.y*inv, x0.z*inv, x0.w*inv,
                      x1.x*inv, x1.y*inv, x1.z*inv, x1.w*inv };
    __nv_bfloat16 h[8], l[8];
#pragma unroll
    for (int q = 0; q < 8; ++q) split_bf16(vals[q], h[q], l[q]);
#pragma unroll
    for (int q = 0; q < 2; ++q) {
        int idx = 4 * lane + 2 * q;
        *reinterpret_cast<__nv_bfloat162*>(hp + idx) = __nv_bfloat162(h[2*q], h[2*q+1]);
        *reinterpret_cast<__nv_bfloat162*>(lp + idx) = __nv_bfloat162(l[2*q], l[2*q+1]);
        int idx2 = 128 + 4 * lane + 2 * q;
        *reinterpret_cast<__nv_bfloat162*>(hp + idx2) = __nv_bfloat162(h[4+2*q], h[4+2*q+1]);
        *reinterpret_cast<__nv_bfloat162*>(lp + idx2) = __nv_bfloat162(l[4+2*q], l[4+2*q+1]);
    }

    if (lane == 0) { g_S[gw] = 0.f; g_P[gw] = 0.f; g_cnt[gw] = 0.f; }
}

// ---------------------------------------------------------------------------
// K1: focal modulation
// ---------------------------------------------------------------------------
__device__ __forceinline__ float warp_max(float v) {
#pragma unroll
    for (int o = 16; o > 0; o >>= 1) v = fmaxf(v, __shfl_xor_sync(0xffffffffu, v, o));
    return v;
}
__device__ __forceinline__ float warp_sum(float v) {
#pragma unroll
    for (int o = 16; o > 0; o >>= 1) v += __shfl_xor_sync(0xffffffffu, v, o);
    return v;
}

__global__ void mod_kernel(const float* __restrict__ preds, const int* __restrict__ labels) {
    __shared__ float sh4[4];
    int b = blockIdx.x, t = threadIdx.x, lane = t & 31, w = t >> 5;
    const float* row = preds + (size_t)b * CC;

    float mx = -1e30f;
    for (int c = t; c < CC; c += 128) mx = fmaxf(mx, row[c]);
    mx = warp_max(mx);
    if (lane == 0) sh4[w] = mx;
    __syncthreads();
    mx = fmaxf(fmaxf(sh4[0], sh4[1]), fmaxf(sh4[2], sh4[3]));
    __syncthreads();

    float s = 0.f;
    for (int c = t; c < CC; c += 128) s += __expf(row[c] - mx);
    s = warp_sum(s);
    if (lane == 0) sh4[w] = s;
    __syncthreads();

    if (t == 0) {
        float ssum = sh4[0] + sh4[1] + sh4[2] + sh4[3];
        float nll  = row[labels[b]] - mx - logf(ssum);
        float pt   = __expf(nll);
        float om   = 1.f - pt;
        g_mod[b]   = om * om;
    }
}

// ---------------------------------------------------------------------------
// K2: tensor-core split-bf16 Gram GEMM + fused epilogue.
// Block tile M=128 x N=256, K in 4 chunks of 64 (double-buffered SMEM).
// dot = hi*hi + hi*lo + lo*hi.  l = (dot-1)/T; S += exp(l) (j!=i); P/cnt.
// Path A (sm_103a cubin): tcgen05 SS MMA, fp32 accum in TMEM.
// Path B (compute_103):   mma.sync m16n8k16 bf16, fp32 accum in registers.
// ---------------------------------------------------------------------------
#define OFF_A_HI 0
#define OFF_A_LO 16384
#define OFF_B_HI 32768
#define OFF_B_LO 65536
#define STAGE_BYTES 98304
#define DYN_SMEM (2 * STAGE_BYTES + 1024)

// synchronous tile load (tcgen05 path)
__device__ __forceinline__ void load_tile(char* dst, const __nv_bfloat16* src,
                                          int rows, int row0, int kc, int tid) {
    int nseg = rows * 8;
    for (int seg = tid; seg < nseg; seg += 256) {
        int r = seg >> 3, sc = seg & 7;
        uint4 v = *reinterpret_cast<const uint4*>(
            src + (size_t)(row0 + r) * DD + kc * 64 + sc * 8);
        int off = r * 128 + sc * 16;
        *reinterpret_cast<uint4*>(dst + SMEM_SWIZZLE_128B(off)) = v;
    }
}

// async tile load (mma.sync path)
__device__ __forceinline__ void load_tile_async(uint32_t dstb, const __nv_bfloat16* src,
                                                int rows, int row0, int kc, int tid) {
    int nseg = rows * 8;
    for (int seg = tid; seg < nseg; seg += 256) {
        int r = seg >> 3, sc = seg & 7;
        const void* g = src + (size_t)(row0 + r) * DD + kc * 64 + sc * 8;
        uint32_t off = (uint32_t)(r * 128 + sc * 16);
        CP_ASYNC_16(dstb + SMEM_SWIZZLE_128B(off), g);
    }
}

__global__ void __launch_bounds__(256, 1) main_kernel(const int* __restrict__ labels) {
    extern __shared__ char dsm[];
    __shared__ int   cl[256];
    __shared__ int   rlab[128];
    __shared__ float sS[128], sP[128], sC[128];

    const int tid  = threadIdx.x;
    const int w    = tid >> 5;
    const int lane = tid & 31;
    const int i0   = blockIdx.x * 128;
    const int j0   = blockIdx.y * 256;

    uint32_t dsm_u = smem_to_u32(dsm);
    uint32_t sb    = (dsm_u + 1023u) & ~1023u;   // 1024-aligned SMEM base
    char*    sbp   = dsm + (sb - dsm_u);

    if (tid < 128) { sS[tid] = 0.f; sP[tid] = 0.f; sC[tid] = 0.f;
                     rlab[tid] = labels[(i0 + tid) & (BB - 1)]; }
    cl[tid] = labels[(j0 + tid) & (BB - 1)];

    const float invT = 1.0f / TEMP;

#if defined(__CUDA_ARCH_FEAT_SM103_ALL) || defined(__CUDA_ARCH_FEAT_SM100_ALL)
    // ===================== Path A: tcgen05 =====================
    __shared__ uint32_t s_tmem;
    __shared__ uint64_t s_mbar[2];

    if (w == 0) TCGEN05_ALLOC(smem_to_u32(&s_tmem), 256);
    if (tid == 0) {
        MBARRIER_INIT(smem_to_u32(&s_mbar[0]), 1);
        MBARRIER_INIT(smem_to_u32(&s_mbar[1]), 1);
    }
    __syncthreads();
    const uint32_t tmem = s_tmem;

    for (int kc = 0; kc < 4; ++kc) {
        const int buf = kc & 1;
        const uint32_t stb = sb + buf * STAGE_BYTES;
        char* stp = sbp + buf * STAGE_BYTES;

        if (kc >= 2) MBARRIER_WAIT_PARITY(smem_to_u32(&s_mbar[buf]), 0);

        load_tile(stp + OFF_A_HI, g_hi, 128, i0, kc, tid);
        load_tile(stp + OFF_A_LO, g_lo, 128, i0, kc, tid);
        load_tile(stp + OFF_B_HI, g_hi, 256, j0, kc, tid);
        load_tile(stp + OFF_B_LO, g_lo, 256, j0, kc, tid);
        __syncthreads();

        if (w == 0) {
            FENCE_PROXY_ASYNC_SHARED_CTA();
            if (elect_one_pred()) {
                uint64_t aH = MAKE_SMEM_DESC(stb + OFF_A_HI);
                uint64_t aL = MAKE_SMEM_DESC(stb + OFF_A_LO);
                uint64_t bH = MAKE_SMEM_DESC(stb + OFF_B_HI);
                uint64_t bL = MAKE_SMEM_DESC(stb + OFF_B_LO);
#pragma unroll
                for (int st = 0; st < 4; ++st)
                    mma_ss_f16(tmem, aH + st * 2, bH + st * 2, IDESC_MAIN, !(kc == 0 && st == 0));
#pragma unroll
                for (int st = 0; st < 4; ++st)
                    mma_ss_f16(tmem, aH + st * 2, bL + st * 2, IDESC_MAIN, true);
#pragma unroll
                for (int st = 0; st < 4; ++st)
                    mma_ss_f16(tmem, aL + st * 2, bH + st * 2, IDESC_MAIN, true);
                TCGEN05_COMMIT(smem_to_u32(&s_mbar[buf]));
            }
        }
    }

    MBARRIER_WAIT_PARITY(smem_to_u32(&s_mbar[0]), 1);
    MBARRIER_WAIT_PARITY(smem_to_u32(&s_mbar[1]), 1);
    TCGEN05_FENCE_AFTER();

    // Epilogue: warps (w, w+4) share rows (w&3)*32.., split N halves.
    {
        const int subp = w & 3;
        const int colh = (w >> 2) * 128;
        const uint32_t woff = (uint32_t)subp << 21;
        const int rloc = subp * 32 + lane;
        const int i  = i0 + rloc;
        const int rl = rlab[rloc];

        float s = 0.f, p = 0.f, c = 0.f;
#pragma unroll
        for (int t = 0; t < 4; ++t) {
            uint32_t dr[32];
            TCGEN05_LD_32X32B_X32(dr, tmem + woff + (uint32_t)(colh + t * 32));
            TCGEN05_WAIT_LD();
            const int cb = colh + t * 32;
#pragma unroll
            for (int n = 0; n < 32; ++n) {
                int j = j0 + cb + n;
                float l = fmaf(__uint_as_float(dr[n]), invT, -invT);
                if (i != j) {
                    s += __expf(l);
                    if (rl == cl[cb + n]) { p += l; c += 1.f; }
                }
            }
        }
        TCGEN05_FENCE_BEFORE();
        atomicAdd(&sS[rloc], s);
        atomicAdd(&sP[rloc], p);
        atomicAdd(&sC[rloc], c);
    }
    __syncthreads();
    if (tid < 128) {
        atomicAdd(&g_S[i0 + tid],   sS[tid]);
        atomicAdd(&g_P[i0 + tid],   sP[tid]);
        atomicAdd(&g_cnt[i0 + tid], sC[tid]);
    }
    __syncthreads();
    if (tid == 0) {
        mbarrier_inval(smem_to_u32(&s_mbar[0]));
        mbarrier_inval(smem_to_u32(&s_mbar[1]));
    }
    if (w == 0) TCGEN05_DEALLOC(tmem, 256);

#else
    // ===================== Path B: mma.sync bf16 =====================
    const int wm = w >> 2;          // 0..1 -> rows wm*64..+63
    const int wn = w & 3;           // 0..3 -> cols wn*64..+63
    __syncthreads();

    float acc[4][8][4];
#pragma unroll
    for (int mf = 0; mf < 4; ++mf)
#pragma unroll
        for (int nf = 0; nf < 8; ++nf)
#pragma unroll
            for (int q = 0; q < 4; ++q) acc[mf][nf][q] = 0.f;

    // prologue: chunk 0 -> buf 0
    {
        uint32_t stb = sb;
        load_tile_async(stb + OFF_A_HI, g_hi, 128, i0, 0, tid);
        load_tile_async(stb + OFF_A_LO, g_lo, 128, i0, 0, tid);
        load_tile_async(stb + OFF_B_HI, g_hi, 256, j0, 0, tid);
        load_tile_async(stb + OFF_B_LO, g_lo, 256, j0, 0, tid);
        CP_ASYNC_COMMIT();
    }

    for (int kc = 0; kc < 4; ++kc) {
        if (kc < 3) {
            uint32_t stb = sb + ((kc + 1) & 1) * STAGE_BYTES;
            load_tile_async(stb + OFF_A_HI, g_hi, 128, i0, kc + 1, tid);
            load_tile_async(stb + OFF_A_LO, g_lo, 128, i0, kc + 1, tid);
            load_tile_async(stb + OFF_B_HI, g_hi, 256, j0, kc + 1, tid);
            load_tile_async(stb + OFF_B_LO, g_lo, 256, j0, kc + 1, tid);
            CP_ASYNC_COMMIT();
            CP_ASYNC_WAIT(1);
        } else {
            CP_ASYNC_WAIT(0);
        }
        __syncthreads();

        const uint32_t stb = sb + (kc & 1) * STAGE_BYTES;
#pragma unroll
        for (int ks = 0; ks < 4; ++ks) {
            uint32_t ah[4][4], al[4][4];
#pragma unroll
            for (int mf = 0; mf < 4; ++mf) {
                int row  = wm * 64 + mf * 16 + (lane & 15);
                int koff = ks * 16 + ((lane >> 4) << 3);
                uint32_t byoff = SMEM_SWIZZLE_128B((uint32_t)(row * 128 + koff * 2));
                LDSM_X4(ah[mf][0], ah[mf][1], ah[mf][2], ah[mf][3], stb + OFF_A_HI + byoff);
                LDSM_X4(al[mf][0], al[mf][1], al[mf][2], al[mf][3], stb + OFF_A_LO + byoff);
            }
#pragma unroll
            for (int nf2 = 0; nf2 < 4; ++nf2) {
                int brow = wn * 64 + nf2 * 16 + (lane & 7) + ((lane >> 4) << 3);
                int bk   = ks * 16 + (((lane >> 3) & 1) << 3);
                uint32_t boff = SMEM_SWIZZLE_128B((uint32_t)(brow * 128 + bk * 2));
                uint32_t bh[4], bl[4];
                LDSM_X4(bh[0], bh[1], bh[2], bh[3], stb + OFF_B_HI + boff);
                LDSM_X4(bl[0], bl[1], bl[2], bl[3], stb + OFF_B_LO + boff);
#pragma unroll
                for (int mf = 0; mf < 4; ++mf) {
                    MMA_BF16(acc[mf][2*nf2],   ah[mf], bh[0], bh[1]);
                    MMA_BF16(acc[mf][2*nf2+1], ah[mf], bh[2], bh[3]);
                    MMA_BF16(acc[mf][2*nf2],   ah[mf], bl[0], bl[1]);
                    MMA_BF16(acc[mf][2*nf2+1], ah[mf], bl[2], bl[3]);
                    MMA_BF16(acc[mf][2*nf2],   al[mf], bh[0], bh[1]);
                    MMA_BF16(acc[mf][2*nf2+1], al[mf], bh[2], bh[3]);
                }
            }
        }
        __syncthreads();
    }

    // Epilogue: fragment layout D 16x8: lane holds rows (g, g+8), cols 2t,2t+1
    {
        const int g  = lane >> 2;
        const int t2 = (lane & 3) * 2;
#pragma unroll
        for (int mf = 0; mf < 4; ++mf) {
            const int r0 = wm * 64 + mf * 16 + g;   // local rows r0, r0+8
            float sA[2] = {0.f, 0.f}, pA[2] = {0.f, 0.f}, cA[2] = {0.f, 0.f};
            const int iA[2] = { i0 + r0, i0 + r0 + 8 };
            const int lA[2] = { rlab[r0], rlab[r0 + 8] };
#pragma unroll
            for (int nf = 0; nf < 8; ++nf) {
                const int cb = wn * 64 + nf * 8 + t2;
#pragma unroll
                for (int h = 0; h < 2; ++h) {
#pragma unroll
                    for (int q = 0; q < 2; ++q) {
                        int jloc = cb + q;
                        int j = j0 + jloc;
                        float l = fmaf(acc[mf][nf][h * 2 + q], invT, -invT);
                        if (iA[h] != j) {
                            sA[h] += __expf(l);
                            if (lA[h] == cl[jloc]) { pA[h] += l; cA[h] += 1.f; }
                        }
                    }
                }
            }
            // quad reduce (lanes sharing the same row)
#pragma unroll
            for (int h = 0; h < 2; ++h) {
#pragma unroll
                for (int o = 1; o <= 2; o <<= 1) {
                    sA[h] += __shfl_xor_sync(0xffffffffu, sA[h], o);
                    pA[h] += __shfl_xor_sync(0xffffffffu, pA[h], o);
                    cA[h] += __shfl_xor_sync(0xffffffffu, cA[h], o);
                }
            }
            if ((lane & 3) == 0) {
                atomicAdd(&sS[r0], sA[0]);     atomicAdd(&sS[r0 + 8], sA[1]);
                atomicAdd(&sP[r0], pA[0]);     atomicAdd(&sP[r0 + 8], pA[1]);
                atomicAdd(&sC[r0], cA[0]);     atomicAdd(&sC[r0 + 8], cA[1]);
            }
        }
    }
    __syncthreads();
    if (tid < 128) {
        atomicAdd(&g_S[i0 + tid],   sS[tid]);
        atomicAdd(&g_P[i0 + tid],   sP[tid]);
        atomicAdd(&g_cnt[i0 + tid], sC[tid]);
    }
#endif
}

// ---------------------------------------------------------------------------
// K3: per-row loss partials (32 blocks), then K4 writeout
// ---------------------------------------------------------------------------
__global__ void finalize_kernel() {
    __shared__ float red[128];
    int t = threadIdx.x;
    int i = blockIdx.x * 128 + t;
    float v = g_mod[i & (BB - 1)] * (g_P[i] / g_cnt[i] - logf(g_S[i]));
    red[t] = v;
    __syncthreads();
#pragma unroll
    for (int sft = 64; sft > 0; sft >>= 1) {
        if (t < sft) red[t] += red[t + sft];
        __syncthreads();
    }
    if (t == 0) g_part[blockIdx.x] = red[0];
}

__global__ void writeout_kernel(float* __restrict__ out) {
    float v = g_part[threadIdx.x];
#pragma unroll
    for (int o = 16; o > 0; o >>= 1) v += __shfl_xor_sync(0xffffffffu, v, o);
    if (threadIdx.x == 0) out[0] = -v / (float)NN;
}

// ---------------------------------------------------------------------------
extern "C" void kernel_launch(void* const* d_in, const int* in_sizes, int n_in,
                              void* d_out, int out_size) {
    const float* feats  = (const float*)d_in[0];   // [B, V, D]
    const float* preds  = (const float*)d_in[1];   // [B, C]
    const int*   labels = (const int*)d_in[2];     // [B]
    float* out = (float*)d_out;

    cudaFuncSetAttribute(main_kernel, cudaFuncAttributeMaxDynamicSharedMemorySize, DYN_SMEM);

    norm_kernel<<<NN / 8, 256>>>(feats);
    mod_kernel<<<BB, 128>>>(preds, labels);
    main_kernel<<<dim3(NN / 128, NN / 256), 256, DYN_SMEM>>>(labels);
    finalize_kernel<<<32, 128>>>();
    writeout_kernel<<<1, 32>>>(out);
}

// round 6
// speedup vs baseline: 3.6881x; 1.1728x over previous
#include <cuda_runtime.h>
#include <cuda_fp16.h>
#include <math.h>
#include <stdint.h>

// Problem constants (fixed shapes)
#define NN   4096      // N = V*B
#define BB   2048      // batch
#define VV   2         // views
#define DD   256       // feature dim
#define CC   1000      // classes
#define TEMP 0.07f

// Scratch (no cudaMalloc allowed)
__device__ __half g_f16[NN * DD];         // fp16 normalized features, view-major
__device__ float g_mod[BB];               // focal modulation per sample
__device__ float g_S[NN];                 // sum exp(l - M) over j != i
__device__ float g_P[NN];                 // sum over positives of (l - M)
__device__ float g_cnt[NN];               // positive counts
__device__ float g_part[32];              // finalize partials
__device__ unsigned g_done;               // finalize completion counter

// ============================================================================
// PTX helpers (valid on compute_103 base target)
// ============================================================================
__device__ __forceinline__ uint32_t smem_to_u32(const void* p) {
    uint32_t a;
    asm("{ .reg .u64 t; cvta.to.shared.u64 t, %1; cvt.u32.u64 %0, t; }"
        : "=r"(a) : "l"(p));
    return a;
}
#define SMEM_SWIZZLE_128B(byte_offset) \
    ((byte_offset) ^ (((byte_offset) >> 3) & 0x70))

// mma.sync fp16 (sm_70+): D(16x8 f32) += A(16x16 f16) * B(16x8 f16)
#define MMA_F16(d, a, b0, b1) \
    asm volatile("mma.sync.aligned.m16n8k16.row.col.f32.f16.f16.f32 " \
        "{%0,%1,%2,%3}, {%4,%5,%6,%7}, {%8,%9}, {%0,%1,%2,%3};" \
        : "+f"((d)[0]), "+f"((d)[1]), "+f"((d)[2]), "+f"((d)[3]) \
        : "r"((a)[0]), "r"((a)[1]), "r"((a)[2]), "r"((a)[3]), \
          "r"(b0), "r"(b1))

#define LDSM_X4(r0, r1, r2, r3, addr) \
    asm volatile("ldmatrix.sync.aligned.m8n8.x4.shared.b16 {%0,%1,%2,%3}, [%4];" \
        : "=r"(r0), "=r"(r1), "=r"(r2), "=r"(r3) : "r"(addr))

#define CP_ASYNC_16(dst, src) \
    asm volatile("cp.async.cg.shared.global [%0], [%1], 16;" \
        :: "r"(dst), "l"(src) : "memory")
#define CP_ASYNC_COMMIT() asm volatile("cp.async.commit_group;" ::: "memory")
#define CP_ASYNC_WAIT(n)  asm volatile("cp.async.wait_group %0;" :: "n"(n) : "memory")

// ---------------------------------------------------------------------------
// K0: normalize rows + view-major restack -> fp16; zero accumulators
// features [B, V, D] -> row v*B+b of g_f16. One warp per output row.
// ---------------------------------------------------------------------------
__global__ void norm_kernel(const float* __restrict__ feats) {
    int gw   = (blockIdx.x * blockDim.x + threadIdx.x) >> 5;
    int lane = threadIdx.x & 31;
    if (gw >= NN) return;
    int b = gw & (BB - 1);
    int v = gw >> 11;

    const float4* src = reinterpret_cast<const float4*>(feats + (size_t)(b * VV + v) * DD);
    float4 x0 = src[lane];
    float4 x1 = src[lane + 32];

    float ss = x0.x * x0.x + x0.y * x0.y + x0.z * x0.z + x0.w * x0.w
             + x1.x * x1.x + x1.y * x1.y + x1.z * x1.z + x1.w * x1.w;
#pragma unroll
    for (int o = 16; o > 0; o >>= 1) ss += __shfl_xor_sync(0xffffffffu, ss, o);
    float inv = rsqrtf(ss);

    __half2 h0 = __floats2half2_rn(x0.x * inv, x0.y * inv);
    __half2 h1 = __floats2half2_rn(x0.z * inv, x0.w * inv);
    __half2 h2 = __floats2half2_rn(x1.x * inv, x1.y * inv);
    __half2 h3 = __floats2half2_rn(x1.z * inv, x1.w * inv);

    __half2* hp = reinterpret_cast<__half2*>(g_f16 + (size_t)gw * DD);
    hp[2 * lane]          = h0;
    hp[2 * lane + 1]      = h1;
    hp[64 + 2 * lane]     = h2;
    hp[64 + 2 * lane + 1] = h3;

    if (lane == 0) { g_S[gw] = 0.f; g_P[gw] = 0.f; g_cnt[gw] = 0.f; }
}

// ---------------------------------------------------------------------------
// K1: focal modulation: mod_b = (1 - exp(log_softmax(preds_b)[label_b]))^2
// ---------------------------------------------------------------------------
__device__ __forceinline__ float warp_max(float v) {
#pragma unroll
    for (int o = 16; o > 0; o >>= 1) v = fmaxf(v, __shfl_xor_sync(0xffffffffu, v, o));
    return v;
}
__device__ __forceinline__ float warp_sum(float v) {
#pragma unroll
    for (int o = 16; o > 0; o >>= 1) v += __shfl_xor_sync(0xffffffffu, v, o);
    return v;
}

__global__ void mod_kernel(const float* __restrict__ preds, const int* __restrict__ labels) {
    __shared__ float sh4[4];
    int b = blockIdx.x, t = threadIdx.x, lane = t & 31, w = t >> 5;
    const float* row = preds + (size_t)b * CC;

    float mx = -1e30f;
    for (int c = t; c < CC; c += 128) mx = fmaxf(mx, row[c]);
    mx = warp_max(mx);
    if (lane == 0) sh4[w] = mx;
    __syncthreads();
    mx = fmaxf(fmaxf(sh4[0], sh4[1]), fmaxf(sh4[2], sh4[3]));
    __syncthreads();

    float s = 0.f;
    for (int c = t; c < CC; c += 128) s += __expf(row[c] - mx);
    s = warp_sum(s);
    if (lane == 0) sh4[w] = s;
    __syncthreads();

    if (t == 0) {
        float ssum = sh4[0] + sh4[1] + sh4[2] + sh4[3];
        float nll  = row[labels[b]] - mx - logf(ssum);
        float pt   = __expf(nll);
        float om   = 1.f - pt;
        g_mod[b]   = om * om;
    }
}

// ---------------------------------------------------------------------------
// K2: fp16 tensor-core Gram GEMM + fused epilogue.
// Block tile M=128 x N=256, K in 4 chunks of 64, cp.async double-buffered.
// 8 warps, warp tile 64x64, mma.sync m16n8k16 f16->f32.
// l = (dot-1)/T; S += exp(l) (j!=i); P/cnt on label match.
// ---------------------------------------------------------------------------
#define OFF_A 0
#define OFF_B 16384
#define STAGE_BYTES 49152
#define DYN_SMEM (2 * STAGE_BYTES + 1024)

__device__ __forceinline__ void load_tile_async(uint32_t dstb, const __half* src,
                                                int rows, int row0, int kc, int tid) {
    int nseg = rows * 8;
    for (int seg = tid; seg < nseg; seg += 256) {
        int r = seg >> 3, sc = seg & 7;
        const void* g = src + (size_t)(row0 + r) * DD + kc * 64 + sc * 8;
        uint32_t off = (uint32_t)(r * 128 + sc * 16);
        CP_ASYNC_16(dstb + SMEM_SWIZZLE_128B(off), g);
    }
}

__global__ void __launch_bounds__(256, 1) main_kernel(const int* __restrict__ labels) {
    extern __shared__ char dsm[];
    __shared__ int   cl[256];
    __shared__ int   rlab[128];
    __shared__ float sS[128], sP[128], sC[128];

    const int tid  = threadIdx.x;
    const int w    = tid >> 5;
    const int lane = tid & 31;
    const int i0   = blockIdx.x * 128;
    const int j0   = blockIdx.y * 256;

    uint32_t dsm_u = smem_to_u32(dsm);
    uint32_t sb    = (dsm_u + 1023u) & ~1023u;   // 1024-aligned SMEM base

    if (tid < 128) { sS[tid] = 0.f; sP[tid] = 0.f; sC[tid] = 0.f;
                     rlab[tid] = labels[(i0 + tid) & (BB - 1)]; }
    cl[tid] = labels[(j0 + tid) & (BB - 1)];

    const float invT = 1.0f / TEMP;
    const int wm = w >> 2;          // 0..1 -> rows wm*64..+63
    const int wn = w & 3;           // 0..3 -> cols wn*64..+63
    __syncthreads();

    float acc[4][8][4];
#pragma unroll
    for (int mf = 0; mf < 4; ++mf)
#pragma unroll
        for (int nf = 0; nf < 8; ++nf)
#pragma unroll
            for (int q = 0; q < 4; ++q) acc[mf][nf][q] = 0.f;

    // prologue: chunk 0 -> buf 0
    load_tile_async(sb + OFF_A, g_f16, 128, i0, 0, tid);
    load_tile_async(sb + OFF_B, g_f16, 256, j0, 0, tid);
    CP_ASYNC_COMMIT();

    for (int kc = 0; kc < 4; ++kc) {
        if (kc < 3) {
            uint32_t stb = sb + ((kc + 1) & 1) * STAGE_BYTES;
            load_tile_async(stb + OFF_A, g_f16, 128, i0, kc + 1, tid);
            load_tile_async(stb + OFF_B, g_f16, 256, j0, kc + 1, tid);
            CP_ASYNC_COMMIT();
            CP_ASYNC_WAIT(1);
        } else {
            CP_ASYNC_WAIT(0);
        }
        __syncthreads();

        const uint32_t stb = sb + (kc & 1) * STAGE_BYTES;
#pragma unroll
        for (int ks = 0; ks < 4; ++ks) {
            uint32_t ah[4][4];
#pragma unroll
            for (int mf = 0; mf < 4; ++mf) {
                int row  = wm * 64 + mf * 16 + (lane & 15);
                int koff = ks * 16 + ((lane >> 4) << 3);
                uint32_t byoff = SMEM_SWIZZLE_128B((uint32_t)(row * 128 + koff * 2));
                LDSM_X4(ah[mf][0], ah[mf][1], ah[mf][2], ah[mf][3], stb + OFF_A + byoff);
            }
#pragma unroll
            for (int nf2 = 0; nf2 < 4; ++nf2) {
                int brow = wn * 64 + nf2 * 16 + (lane & 7) + ((lane >> 4) << 3);
                int bk   = ks * 16 + (((lane >> 3) & 1) << 3);
                uint32_t boff = SMEM_SWIZZLE_128B((uint32_t)(brow * 128 + bk * 2));
                uint32_t bh[4];
                LDSM_X4(bh[0], bh[1], bh[2], bh[3], stb + OFF_B + boff);
#pragma unroll
                for (int mf = 0; mf < 4; ++mf) {
                    MMA_F16(acc[mf][2*nf2],   ah[mf], bh[0], bh[1]);
                    MMA_F16(acc[mf][2*nf2+1], ah[mf], bh[2], bh[3]);
                }
            }
        }
        __syncthreads();
    }

    // Epilogue: fragment layout D 16x8: lane holds rows (g, g+8), cols 2t,2t+1
    {
        const int g  = lane >> 2;
        const int t2 = (lane & 3) * 2;
#pragma unroll
        for (int mf = 0; mf < 4; ++mf) {
            const int r0 = wm * 64 + mf * 16 + g;   // local rows r0, r0+8
            float sA[2] = {0.f, 0.f}, pA[2] = {0.f, 0.f}, cA[2] = {0.f, 0.f};
            const int iA[2] = { i0 + r0, i0 + r0 + 8 };
            const int lA[2] = { rlab[r0], rlab[r0 + 8] };
#pragma unroll
            for (int nf = 0; nf < 8; ++nf) {
                const int cb = wn * 64 + nf * 8 + t2;
#pragma unroll
                for (int h = 0; h < 2; ++h) {
#pragma unroll
                    for (int q = 0; q < 2; ++q) {
                        int jloc = cb + q;
                        int j = j0 + jloc;
                        float l = fmaf(acc[mf][nf][h * 2 + q], invT, -invT);
                        if (iA[h] != j) {
                            sA[h] += __expf(l);
                            if (lA[h] == cl[jloc]) { pA[h] += l; cA[h] += 1.f; }
                        }
                    }
                }
            }
#pragma unroll
            for (int h = 0; h < 2; ++h) {
#pragma unroll
                for (int o = 1; o <= 2; o <<= 1) {
                    sA[h] += __shfl_xor_sync(0xffffffffu, sA[h], o);
                    pA[h] += __shfl_xor_sync(0xffffffffu, pA[h], o);
                    cA[h] += __shfl_xor_sync(0xffffffffu, cA[h], o);
                }
            }
            if ((lane & 3) == 0) {
                atomicAdd(&sS[r0], sA[0]);     atomicAdd(&sS[r0 + 8], sA[1]);
                atomicAdd(&sP[r0], pA[0]);     atomicAdd(&sP[r0 + 8], pA[1]);
                atomicAdd(&sC[r0], cA[0]);     atomicAdd(&sC[r0 + 8], cA[1]);
            }
        }
    }
    __syncthreads();
    if (tid < 128) {
        atomicAdd(&g_S[i0 + tid],   sS[tid]);
        atomicAdd(&g_P[i0 + tid],   sP[tid]);
        atomicAdd(&g_cnt[i0 + tid], sC[tid]);
    }
}

// ---------------------------------------------------------------------------
// K3: per-row loss partials (32 blocks) + fused last-block writeout
// ---------------------------------------------------------------------------
__global__ void finalize_kernel(float* __restrict__ out) {
    __shared__ float red[128];
    __shared__ unsigned isLast;
    int t = threadIdx.x;
    int i = blockIdx.x * 128 + t;
    float v = g_mod[i & (BB - 1)] * (g_P[i] / g_cnt[i] - logf(g_S[i]));
    red[t] = v;
    __syncthreads();
#pragma unroll
    for (int sft = 64; sft > 0; sft >>= 1) {
        if (t < sft) red[t] += red[t + sft];
        __syncthreads();
    }
    if (t == 0) {
        g_part[blockIdx.x] = red[0];
        __threadfence();
        isLast = (atomicAdd(&g_done, 1u) == 31u) ? 1u : 0u;
    }
    __syncthreads();
    if (isLast && t < 32) {
        __threadfence();
        float s = g_part[t];
#pragma unroll
        for (int o = 16; o > 0; o >>= 1) s += __shfl_xor_sync(0xffffffffu, s, o);
        if (t == 0) { out[0] = -s / (float)NN; g_done = 0u; }
    }
}

// ---------------------------------------------------------------------------
extern "C" void kernel_launch(void* const* d_in, const int* in_sizes, int n_in,
                              void* d_out, int out_size) {
    const float* feats  = (const float*)d_in[0];   // [B, V, D]
    const float* preds  = (const float*)d_in[1];   // [B, C]
    const int*   labels = (const int*)d_in[2];     // [B]
    float* out = (float*)d_out;

    cudaFuncSetAttribute(main_kernel, cudaFuncAttributeMaxDynamicSharedMemorySize, DYN_SMEM);

    norm_kernel<<<NN / 8, 256>>>(feats);
    mod_kernel<<<BB, 128>>>(preds, labels);
    main_kernel<<<dim3(NN / 128, NN / 256), 256, DYN_SMEM>>>(labels);
    finalize_kernel<<<32, 128>>>(out);
}

// round 7
// speedup vs baseline: 7.1619x; 1.9419x over previous
#include <cuda_runtime.h>
#include <cuda_fp16.h>
#include <math.h>
#include <stdint.h>

// Problem constants (fixed shapes)
#define NN   4096      // N = V*B
#define BB   2048      // batch
#define VV   2         // views
#define DD   256       // feature dim
#define CC   1000      // classes
#define TEMP 0.07f
#define NTILE 32       // 4096 / 128
#define NBLK  (NTILE * (NTILE + 1) / 2)   // 528 triangular blocks

// Scratch (no cudaMalloc allowed)
__device__ __half g_f16[NN * DD];         // fp16 normalized features, view-major
__device__ float g_mod[BB];               // focal modulation per sample
__device__ float g_S[NN];                 // sum exp(l - M) over j != i
__device__ float g_P[NN];                 // sum over positives of (l - M)
__device__ float g_cnt[NN];               // positive counts
__device__ unsigned g_done;               // main-kernel completion counter

// ============================================================================
// PTX helpers (valid on compute_103 base target)
// ============================================================================
__device__ __forceinline__ uint32_t smem_to_u32(const void* p) {
    uint32_t a;
    asm("{ .reg .u64 t; cvta.to.shared.u64 t, %1; cvt.u32.u64 %0, t; }"
        : "=r"(a) : "l"(p));
    return a;
}
#define SMEM_SWIZZLE_128B(byte_offset) \
    ((byte_offset) ^ (((byte_offset) >> 3) & 0x70))

// mma.sync fp16 (sm_70+): D(16x8 f32) += A(16x16 f16) * B(16x8 f16)
#define MMA_F16(d, a, b0, b1) \
    asm volatile("mma.sync.aligned.m16n8k16.row.col.f32.f16.f16.f32 " \
        "{%0,%1,%2,%3}, {%4,%5,%6,%7}, {%8,%9}, {%0,%1,%2,%3};" \
        : "+f"((d)[0]), "+f"((d)[1]), "+f"((d)[2]), "+f"((d)[3]) \
        : "r"((a)[0]), "r"((a)[1]), "r"((a)[2]), "r"((a)[3]), \
          "r"(b0), "r"(b1))

#define LDSM_X4(r0, r1, r2, r3, addr) \
    asm volatile("ldmatrix.sync.aligned.m8n8.x4.shared.b16 {%0,%1,%2,%3}, [%4];" \
        : "=r"(r0), "=r"(r1), "=r"(r2), "=r"(r3) : "r"(addr))

#define CP_ASYNC_16(dst, src) \
    asm volatile("cp.async.cg.shared.global [%0], [%1], 16;" \
        :: "r"(dst), "l"(src) : "memory")
#define CP_ASYNC_COMMIT() asm volatile("cp.async.commit_group;" ::: "memory")
#define CP_ASYNC_WAIT(n)  asm volatile("cp.async.wait_group %0;" :: "n"(n) : "memory")

// ---------------------------------------------------------------------------
// K0 (prep): blocks [0,512): normalize+restack -> fp16, zero accumulators.
//            blocks [512,2560): focal modulation per sample (256 threads).
// ---------------------------------------------------------------------------
__global__ void __launch_bounds__(256) prep_kernel(
    const float* __restrict__ feats, const float* __restrict__ preds,
    const int* __restrict__ labels)
{
    const int tid = threadIdx.x, lane = tid & 31, w = tid >> 5;

    if (blockIdx.x < 512) {
        // ---- norm: one warp per output row ----
        int gw = blockIdx.x * 8 + w;
        int b = gw & (BB - 1);
        int v = gw >> 11;

        const float4* src = reinterpret_cast<const float4*>(feats + (size_t)(b * VV + v) * DD);
        float4 x0 = src[lane];
        float4 x1 = src[lane + 32];

        float ss = x0.x*x0.x + x0.y*x0.y + x0.z*x0.z + x0.w*x0.w
                 + x1.x*x1.x + x1.y*x1.y + x1.z*x1.z + x1.w*x1.w;
#pragma unroll
        for (int o = 16; o > 0; o >>= 1) ss += __shfl_xor_sync(0xffffffffu, ss, o);
        float inv = rsqrtf(ss);

        __half2 h0 = __floats2half2_rn(x0.x * inv, x0.y * inv);
        __half2 h1 = __floats2half2_rn(x0.z * inv, x0.w * inv);
        __half2 h2 = __floats2half2_rn(x1.x * inv, x1.y * inv);
        __half2 h3 = __floats2half2_rn(x1.z * inv, x1.w * inv);

        __half2* hp = reinterpret_cast<__half2*>(g_f16 + (size_t)gw * DD);
        hp[2 * lane]          = h0;
        hp[2 * lane + 1]      = h1;
        hp[64 + 2 * lane]     = h2;
        hp[64 + 2 * lane + 1] = h3;

        if (lane == 0) { g_S[gw] = 0.f; g_P[gw] = 0.f; g_cnt[gw] = 0.f; }
    } else {
        // ---- mod: one block per sample ----
        __shared__ float sh8[8];
        int b = blockIdx.x - 512;
        const float* row = preds + (size_t)b * CC;

        float mx = -1e30f;
        for (int c = tid; c < CC; c += 256) mx = fmaxf(mx, row[c]);
#pragma unroll
        for (int o = 16; o > 0; o >>= 1) mx = fmaxf(mx, __shfl_xor_sync(0xffffffffu, mx, o));
        if (lane == 0) sh8[w] = mx;
        __syncthreads();
        mx = sh8[0];
#pragma unroll
        for (int q = 1; q < 8; ++q) mx = fmaxf(mx, sh8[q]);
        __syncthreads();

        float s = 0.f;
        for (int c = tid; c < CC; c += 256) s += __expf(row[c] - mx);
#pragma unroll
        for (int o = 16; o > 0; o >>= 1) s += __shfl_xor_sync(0xffffffffu, s, o);
        if (lane == 0) sh8[w] = s;
        __syncthreads();

        if (tid == 0) {
            float ssum = 0.f;
#pragma unroll
            for (int q = 0; q < 8; ++q) ssum += sh8[q];
            float nll = row[labels[b]] - mx - logf(ssum);
            float pt  = __expf(nll);
            float om  = 1.f - pt;
            g_mod[b]  = om * om;
        }
    }
}

// ---------------------------------------------------------------------------
// K1 (main): symmetric fp16 HMMA Gram GEMM over triangular 128x128 tiles.
// Off-diagonal tiles scatter each element to row i AND row j (col reduce).
// Last finishing block performs the final loss reduction (fused finalize).
// ---------------------------------------------------------------------------
#define OFF_A 0
#define OFF_B 16384
#define STAGE_BYTES 32768
#define DYN_SMEM (2 * STAGE_BYTES + 1024)

__device__ __forceinline__ void load_tile_async(uint32_t dstb, const __half* src,
                                                int row0, int kc, int tid) {
    // 128 rows x 64 halfs (128 B) per tile
#pragma unroll
    for (int it = 0; it < 4; ++it) {
        int seg = tid + it * 256;
        int r = seg >> 3, sc = seg & 7;
        const void* g = src + (size_t)(row0 + r) * DD + kc * 64 + sc * 8;
        uint32_t off = (uint32_t)(r * 128 + sc * 16);
        CP_ASYNC_16(dstb + SMEM_SWIZZLE_128B(off), g);
    }
}

__global__ void __launch_bounds__(256, 2) main_kernel(const int* __restrict__ labels,
                                                      float* __restrict__ out) {
    extern __shared__ char dsm[];
    __shared__ int   rlab[128], clab[128];
    __shared__ float sSr[128], sPr[128], sCr[128];
    __shared__ float sSc[128], sPc[128], sCc[128];
    __shared__ unsigned isLast;

    const int tid  = threadIdx.x;
    const int w    = tid >> 5;
    const int lane = tid & 31;

    // triangular decode: block -> (bi, bj), bi <= bj
    int bi = 0, rem = blockIdx.x;
    while (rem >= NTILE - bi) { rem -= NTILE - bi; ++bi; }
    const int bj = bi + rem;
    const int i0 = bi * 128, j0 = bj * 128;
    const bool diag = (bi == bj);

    uint32_t dsm_u = smem_to_u32(dsm);
    uint32_t sb    = (dsm_u + 1023u) & ~1023u;

    if (tid < 128) {
        sSr[tid] = 0.f; sPr[tid] = 0.f; sCr[tid] = 0.f;
        sSc[tid] = 0.f; sPc[tid] = 0.f; sCc[tid] = 0.f;
        rlab[tid] = labels[(i0 + tid) & (BB - 1)];
        clab[tid] = labels[(j0 + tid) & (BB - 1)];
    }

    const float invT = 1.0f / TEMP;
    const int wm = w >> 2;          // 0..1 -> rows wm*64..+63
    const int wn = w & 3;           // 0..3 -> cols wn*32..+31
    __syncthreads();

    float acc[4][4][4];
#pragma unroll
    for (int mf = 0; mf < 4; ++mf)
#pragma unroll
        for (int nf = 0; nf < 4; ++nf)
#pragma unroll
            for (int q = 0; q < 4; ++q) acc[mf][nf][q] = 0.f;

    // prologue: chunk 0 -> buf 0
    load_tile_async(sb + OFF_A, g_f16, i0, 0, tid);
    load_tile_async(sb + OFF_B, g_f16, j0, 0, tid);
    CP_ASYNC_COMMIT();

    for (int kc = 0; kc < 4; ++kc) {
        if (kc < 3) {
            uint32_t stb = sb + ((kc + 1) & 1) * STAGE_BYTES;
            load_tile_async(stb + OFF_A, g_f16, i0, kc + 1, tid);
            load_tile_async(stb + OFF_B, g_f16, j0, kc + 1, tid);
            CP_ASYNC_COMMIT();
            CP_ASYNC_WAIT(1);
        } else {
            CP_ASYNC_WAIT(0);
        }
        __syncthreads();

        const uint32_t stb = sb + (kc & 1) * STAGE_BYTES;
#pragma unroll
        for (int ks = 0; ks < 4; ++ks) {
            uint32_t ah[4][4];
#pragma unroll
            for (int mf = 0; mf < 4; ++mf) {
                int row  = wm * 64 + mf * 16 + (lane & 15);
                int koff = ks * 16 + ((lane >> 4) << 3);
                uint32_t byoff = SMEM_SWIZZLE_128B((uint32_t)(row * 128 + koff * 2));
                LDSM_X4(ah[mf][0], ah[mf][1], ah[mf][2], ah[mf][3], stb + OFF_A + byoff);
            }
#pragma unroll
            for (int nf2 = 0; nf2 < 2; ++nf2) {
                int brow = wn * 32 + nf2 * 16 + (lane & 7) + ((lane >> 4) << 3);
                int bk   = ks * 16 + (((lane >> 3) & 1) << 3);
                uint32_t boff = SMEM_SWIZZLE_128B((uint32_t)(brow * 128 + bk * 2));
                uint32_t bh[4];
                LDSM_X4(bh[0], bh[1], bh[2], bh[3], stb + OFF_B + boff);
#pragma unroll
                for (int mf = 0; mf < 4; ++mf) {
                    MMA_F16(acc[mf][2*nf2],   ah[mf], bh[0], bh[1]);
                    MMA_F16(acc[mf][2*nf2+1], ah[mf], bh[2], bh[3]);
                }
            }
        }
        __syncthreads();
    }

    // ---------------- Epilogue ----------------
    // Fragment: lane holds rows (g, g+8) of each 16-row mf frag, cols 2t,2t+1.
    {
        const int g  = lane >> 2;
        const int t2 = (lane & 3) * 2;
        float rs[4][2], rp[4][2], rc[4][2];
#pragma unroll
        for (int mf = 0; mf < 4; ++mf)
#pragma unroll
            for (int h = 0; h < 2; ++h) { rs[mf][h] = 0.f; rp[mf][h] = 0.f; rc[mf][h] = 0.f; }

#pragma unroll
        for (int nf = 0; nf < 4; ++nf) {
            const int cb = wn * 32 + nf * 8 + t2;   // local cols cb, cb+1
            float cs[2] = {0.f, 0.f}, cp[2] = {0.f, 0.f}, cc[2] = {0.f, 0.f};
#pragma unroll
            for (int mf = 0; mf < 4; ++mf) {
                const int r0 = wm * 64 + mf * 16 + g;
                const int iA[2] = { i0 + r0, i0 + r0 + 8 };
                const int lA[2] = { rlab[r0], rlab[r0 + 8] };
#pragma unroll
                for (int h = 0; h < 2; ++h) {
#pragma unroll
                    for (int q = 0; q < 2; ++q) {
                        const int jloc = cb + q;
                        float l = fmaf(acc[mf][nf][h * 2 + q], invT, -invT);
                        bool excl = diag && (iA[h] == j0 + jloc);
                        float e  = excl ? 0.f : __expf(l);
                        float mm = (!excl && lA[h] == clab[jloc]) ? 1.f : 0.f;
                        rs[mf][h] += e;      rp[mf][h] += mm * l; rc[mf][h] += mm;
                        cs[q]     += e;      cp[q]     += mm * l; cc[q]     += mm;
                    }
                }
            }
            if (!diag) {
                // reduce column partials across the g axis (lanes xor 4,8,16)
#pragma unroll
                for (int o = 4; o <= 16; o <<= 1) {
#pragma unroll
                    for (int q = 0; q < 2; ++q) {
                        cs[q] += __shfl_xor_sync(0xffffffffu, cs[q], o);
                        cp[q] += __shfl_xor_sync(0xffffffffu, cp[q], o);
                        cc[q] += __shfl_xor_sync(0xffffffffu, cc[q], o);
                    }
                }
                if (g == 0) {
#pragma unroll
                    for (int q = 0; q < 2; ++q) {
                        atomicAdd(&sSc[cb + q], cs[q]);
                        atomicAdd(&sPc[cb + q], cp[q]);
                        atomicAdd(&sCc[cb + q], cc[q]);
                    }
                }
            }
        }
        // reduce row partials across the t axis (lanes xor 1,2)
#pragma unroll
        for (int mf = 0; mf < 4; ++mf) {
            const int r0 = wm * 64 + mf * 16 + g;
#pragma unroll
            for (int h = 0; h < 2; ++h) {
#pragma unroll
                for (int o = 1; o <= 2; o <<= 1) {
                    rs[mf][h] += __shfl_xor_sync(0xffffffffu, rs[mf][h], o);
                    rp[mf][h] += __shfl_xor_sync(0xffffffffu, rp[mf][h], o);
                    rc[mf][h] += __shfl_xor_sync(0xffffffffu, rc[mf][h], o);
                }
            }
            if ((lane & 3) == 0) {
                atomicAdd(&sSr[r0], rs[mf][0]);     atomicAdd(&sSr[r0 + 8], rs[mf][1]);
                atomicAdd(&sPr[r0], rp[mf][0]);     atomicAdd(&sPr[r0 + 8], rp[mf][1]);
                atomicAdd(&sCr[r0], rc[mf][0]);     atomicAdd(&sCr[r0 + 8], rc[mf][1]);
            }
        }
    }
    __syncthreads();
    if (tid < 128) {
        atomicAdd(&g_S[i0 + tid],   sSr[tid]);
        atomicAdd(&g_P[i0 + tid],   sPr[tid]);
        atomicAdd(&g_cnt[i0 + tid], sCr[tid]);
        if (!diag) {
            atomicAdd(&g_S[j0 + tid],   sSc[tid]);
            atomicAdd(&g_P[j0 + tid],   sPc[tid]);
            atomicAdd(&g_cnt[j0 + tid], sCc[tid]);
        }
    }

    // ---------------- Fused finalize (last block) ----------------
    __threadfence();
    __syncthreads();
    if (tid == 0) isLast = (atomicAdd(&g_done, 1u) == NBLK - 1) ? 1u : 0u;
    __syncthreads();
    if (isLast) {
        __threadfence();
        __shared__ float red[256];
        float accv = 0.f;
        for (int i = tid; i < NN; i += 256) {
            float Sv = __ldcg(&g_S[i]);
            float Pv = __ldcg(&g_P[i]);
            float Cv = __ldcg(&g_cnt[i]);
            float mv = __ldcg(&g_mod[i & (BB - 1)]);
            accv += mv * (Pv / Cv - logf(Sv));
        }
        red[tid] = accv;
        __syncthreads();
#pragma unroll
        for (int s = 128; s > 0; s >>= 1) {
            if (tid < s) red[tid] += red[tid + s];
            __syncthreads();
        }
        if (tid == 0) { out[0] = -red[0] / (float)NN; g_done = 0u; }
    }
}

// ---------------------------------------------------------------------------
extern "C" void kernel_launch(void* const* d_in, const int* in_sizes, int n_in,
                              void* d_out, int out_size) {
    const float* feats  = (const float*)d_in[0];   // [B, V, D]
    const float* preds  = (const float*)d_in[1];   // [B, C]
    const int*   labels = (const int*)d_in[2];     // [B]
    float* out = (float*)d_out;

    cudaFuncSetAttribute(main_kernel, cudaFuncAttributeMaxDynamicSharedMemorySize, DYN_SMEM);

    prep_kernel<<<512 + BB, 256>>>(feats, preds, labels);
    main_kernel<<<NBLK, 256, DYN_SMEM>>>(labels, out);
}